// round 1
// baseline (speedup 1.0000x reference)
#include <cuda_runtime.h>

#define FULL 0xffffffffu

__device__ __forceinline__ float relu_(float v) { return fmaxf(v, 0.0f); }

// One warp per batch row, one lane per agent.
//  - Other-agent MLP: fully per-lane in registers, weights broadcast from shared.
//  - Warp butterfly reduce (masked) -> sum_other in every lane.
//  - Selected MLP + gating head: warp-cooperative (lane = neuron).
__global__ __launch_bounds__(512)
void dqv_kernel(const float* __restrict__ x,
                const int*   __restrict__ selp,
                const float* __restrict__ oW1, const float* __restrict__ ob1,
                const float* __restrict__ oW2, const float* __restrict__ ob2,
                const float* __restrict__ oW3, const float* __restrict__ ob3,
                const float* __restrict__ sW1, const float* __restrict__ sb1,
                const float* __restrict__ sW2, const float* __restrict__ sb2,
                const float* __restrict__ sW3, const float* __restrict__ sb3,
                const float* __restrict__ gW1, const float* __restrict__ gb1,
                const float* __restrict__ gW2, const float* __restrict__ gb2,
                float* __restrict__ out_q)
{
    // Weights in shared, transposed so per-output-neuron rows are contiguous
    // (enables broadcast LDS.128: 4 weights per instruction).
    __shared__ __align__(16) float s_oW1t[32 * 4];    // [j][d]
    __shared__             float s_ob1[32];
    __shared__ __align__(16) float s_oW2t[32 * 32];   // [j][i]
    __shared__             float s_ob2[32];
    __shared__ __align__(16) float s_oW3[32 * 16];    // [j][k] (as given)
    __shared__             float s_ob3[16];
    __shared__ __align__(16) float s_sW1t[32 * 4];
    __shared__             float s_sb1[32];
    __shared__ __align__(16) float s_sW2t[32 * 32];
    __shared__             float s_sb2[32];
    __shared__             float s_sW3[32 * 16];
    __shared__             float s_sb3[16];
    __shared__ __align__(16) float s_gW1t[32 * 32];   // [j][m]
    __shared__             float s_gb1[32];
    __shared__             float s_gW2[64];           // [j][a]
    __shared__             float s_gb2[2];

    const int tid = threadIdx.x;

    for (int idx = tid; idx < 128; idx += 512) {
        int d = idx >> 5, j = idx & 31;
        s_oW1t[j * 4 + d] = oW1[idx];
        s_sW1t[j * 4 + d] = sW1[idx];
    }
    for (int idx = tid; idx < 1024; idx += 512) {
        int i = idx >> 5, j = idx & 31;
        s_oW2t[j * 32 + i] = oW2[idx];
        s_sW2t[j * 32 + i] = sW2[idx];
        s_gW1t[j * 32 + i] = gW1[idx];
    }
    for (int idx = tid; idx < 512; idx += 512) {
        s_oW3[idx] = oW3[idx];
        s_sW3[idx] = sW3[idx];
    }
    if (tid < 32) {
        s_ob1[tid] = ob1[tid]; s_ob2[tid] = ob2[tid];
        s_sb1[tid] = sb1[tid]; s_sb2[tid] = sb2[tid];
        s_gb1[tid] = gb1[tid];
    }
    if (tid < 16) { s_ob3[tid] = ob3[tid]; s_sb3[tid] = sb3[tid]; }
    if (tid < 64) s_gW2[tid] = gW2[tid];
    if (tid < 2)  s_gb2[tid] = gb2[tid];
    __syncthreads();

    const int lane = tid & 31;
    const int warp = tid >> 5;
    const int row  = blockIdx.x * 16 + warp;
    const int sel  = selp[0];

    // x[row, agent=lane, 0:4] -- one coalesced float4 per lane
    const float4 xa = reinterpret_cast<const float4*>(x)[row * 32 + lane];

    // ---------------- other-agent MLP (per lane) ----------------
    float h1[32];
    #pragma unroll
    for (int j = 0; j < 32; ++j) {
        float4 w = reinterpret_cast<const float4*>(s_oW1t)[j];
        h1[j] = relu_(fmaf(xa.x, w.x,
                       fmaf(xa.y, w.y,
                       fmaf(xa.z, w.z,
                       fmaf(xa.w, w.w, s_ob1[j])))));
    }

    float acc16[16];
    #pragma unroll
    for (int k = 0; k < 16; ++k) acc16[k] = s_ob3[k];

    // Layer2 + layer3 fused per output neuron j (h2_j never materializes).
    #pragma unroll 4
    for (int j = 0; j < 32; ++j) {
        float a = s_ob2[j];
        #pragma unroll
        for (int q = 0; q < 8; ++q) {
            float4 w = reinterpret_cast<const float4*>(s_oW2t)[j * 8 + q];
            a = fmaf(h1[4 * q + 0], w.x, a);
            a = fmaf(h1[4 * q + 1], w.y, a);
            a = fmaf(h1[4 * q + 2], w.z, a);
            a = fmaf(h1[4 * q + 3], w.w, a);
        }
        a = relu_(a);
        #pragma unroll
        for (int r = 0; r < 4; ++r) {
            float4 w = reinterpret_cast<const float4*>(s_oW3)[j * 4 + r];
            acc16[4 * r + 0] = fmaf(a, w.x, acc16[4 * r + 0]);
            acc16[4 * r + 1] = fmaf(a, w.y, acc16[4 * r + 1]);
            acc16[4 * r + 2] = fmaf(a, w.z, acc16[4 * r + 2]);
            acc16[4 * r + 3] = fmaf(a, w.w, acc16[4 * r + 3]);
        }
    }

    // Final ReLU of mlp3, then mask out the selected agent and reduce.
    const float msk = (lane == sel) ? 0.0f : 1.0f;
    #pragma unroll
    for (int k = 0; k < 16; ++k) acc16[k] = relu_(acc16[k]) * msk;

    #pragma unroll
    for (int off = 16; off; off >>= 1) {
        #pragma unroll
        for (int k = 0; k < 16; ++k)
            acc16[k] += __shfl_xor_sync(FULL, acc16[k], off);
    }
    // acc16[] now holds sum_other[0:16] in every lane.

    // ---------------- selected-agent MLP (warp-cooperative, lane = neuron) ----
    const float sx0 = __shfl_sync(FULL, xa.x, sel);
    const float sx1 = __shfl_sync(FULL, xa.y, sel);
    const float sx2 = __shfl_sync(FULL, xa.z, sel);
    const float sx3 = __shfl_sync(FULL, xa.w, sel);

    float4 w1 = reinterpret_cast<const float4*>(s_sW1t)[lane];
    float sh1 = relu_(fmaf(sx0, w1.x,
                       fmaf(sx1, w1.y,
                       fmaf(sx2, w1.z,
                       fmaf(sx3, w1.w, s_sb1[lane])))));

    float a2 = s_sb2[lane];
    #pragma unroll
    for (int i4 = 0; i4 < 8; ++i4) {
        float4 w = reinterpret_cast<const float4*>(s_sW2t)[lane * 8 + i4];
        a2 = fmaf(__shfl_sync(FULL, sh1, 4 * i4 + 0), w.x, a2);
        a2 = fmaf(__shfl_sync(FULL, sh1, 4 * i4 + 1), w.y, a2);
        a2 = fmaf(__shfl_sync(FULL, sh1, 4 * i4 + 2), w.z, a2);
        a2 = fmaf(__shfl_sync(FULL, sh1, 4 * i4 + 3), w.w, a2);
    }
    const float sh2 = relu_(a2);

    const int k15 = lane & 15;   // lanes 16-31 duplicate lanes 0-15 (harmless)
    float a3 = s_sb3[k15];
    #pragma unroll
    for (int j = 0; j < 32; ++j)
        a3 = fmaf(__shfl_sync(FULL, sh2, j), s_sW3[j * 16 + k15], a3);
    const float sel_out = relu_(a3);

    // ---------------- gating head ----------------
    // concat = [sel_out(16), sum_other(16)]; lane j computes hidden neuron j.
    float ag = s_gb1[lane];
    #pragma unroll
    for (int m4 = 0; m4 < 4; ++m4) {
        float4 w = reinterpret_cast<const float4*>(s_gW1t)[lane * 8 + m4];
        ag = fmaf(__shfl_sync(FULL, sel_out, 4 * m4 + 0), w.x, ag);
        ag = fmaf(__shfl_sync(FULL, sel_out, 4 * m4 + 1), w.y, ag);
        ag = fmaf(__shfl_sync(FULL, sel_out, 4 * m4 + 2), w.z, ag);
        ag = fmaf(__shfl_sync(FULL, sel_out, 4 * m4 + 3), w.w, ag);
    }
    #pragma unroll
    for (int m4 = 0; m4 < 4; ++m4) {
        float4 w = reinterpret_cast<const float4*>(s_gW1t)[lane * 8 + 4 + m4];
        ag = fmaf(acc16[4 * m4 + 0], w.x, ag);
        ag = fmaf(acc16[4 * m4 + 1], w.y, ag);
        ag = fmaf(acc16[4 * m4 + 2], w.z, ag);
        ag = fmaf(acc16[4 * m4 + 3], w.w, ag);
    }
    const float hg = relu_(ag);

    float q0 = hg * s_gW2[lane * 2 + 0];
    float q1 = hg * s_gW2[lane * 2 + 1];
    #pragma unroll
    for (int off = 16; off; off >>= 1) {
        q0 += __shfl_xor_sync(FULL, q0, off);
        q1 += __shfl_xor_sync(FULL, q1, off);
    }

    const float x3 = __shfl_sync(FULL, xa.w, sel);   // sel_in[:,3]
    int act = (int)x3;
    act = act < 0 ? 0 : (act > 1 ? 1 : act);

    if (lane == 0)
        out_q[row] = (act == 0) ? (q0 + s_gb2[0]) : (q1 + s_gb2[1]);
}

extern "C" void kernel_launch(void* const* d_in, const int* in_sizes, int n_in,
                              void* d_out, int out_size)
{
    (void)in_sizes; (void)n_in; (void)out_size;
    // B = 65536 rows, 16 rows per block (512 threads) -> 4096 blocks.
    dqv_kernel<<<4096, 512>>>(
        (const float*)d_in[0],  (const int*)d_in[1],
        (const float*)d_in[2],  (const float*)d_in[3],
        (const float*)d_in[4],  (const float*)d_in[5],
        (const float*)d_in[6],  (const float*)d_in[7],
        (const float*)d_in[8],  (const float*)d_in[9],
        (const float*)d_in[10], (const float*)d_in[11],
        (const float*)d_in[12], (const float*)d_in[13],
        (const float*)d_in[14], (const float*)d_in[15],
        (const float*)d_in[16], (const float*)d_in[17],
        (float*)d_out);
}

// round 2
// speedup vs baseline: 2.1095x; 2.1095x over previous
#include <cuda_runtime.h>

#define FULL 0xffffffffu
typedef unsigned long long ull;

__device__ __forceinline__ float relu_(float v) { return fmaxf(v, 0.0f); }

__device__ __forceinline__ ull ffma2(ull a, ull b, ull c) {
    ull d; asm("fma.rn.f32x2 %0, %1, %2, %3;" : "=l"(d) : "l"(a), "l"(b), "l"(c)); return d;
}
__device__ __forceinline__ ull fadd2(ull a, ull b) {
    ull d; asm("add.rn.f32x2 %0, %1, %2;" : "=l"(d) : "l"(a), "l"(b)); return d;
}
__device__ __forceinline__ ull pk2(float lo, float hi) {
    ull r; asm("mov.b64 %0, {%1, %2};" : "=l"(r) : "f"(lo), "f"(hi)); return r;
}
__device__ __forceinline__ void upk2(ull v, float& lo, float& hi) {
    asm("mov.b64 {%0, %1}, %2;" : "=f"(lo), "=f"(hi) : "l"(v));
}

// Padded stride (floats) for per-lane-row shared tables (kills 128B-stride bank conflicts)
#define PSTR 36

// One warp handles TWO batch rows (R=2); one lane per agent.
// Weights broadcast from shared; each LDS feeds both rows. FFMA2 packed math.
__global__ __launch_bounds__(256, 2)
void dqv_kernel(const float* __restrict__ x,
                const int*   __restrict__ selp,
                const float* __restrict__ oW1, const float* __restrict__ ob1,
                const float* __restrict__ oW2, const float* __restrict__ ob2,
                const float* __restrict__ oW3, const float* __restrict__ ob3,
                const float* __restrict__ sW1, const float* __restrict__ sb1,
                const float* __restrict__ sW2, const float* __restrict__ sb2,
                const float* __restrict__ sW3, const float* __restrict__ sb3,
                const float* __restrict__ gW1, const float* __restrict__ gb1,
                const float* __restrict__ gW2, const float* __restrict__ gb2,
                float* __restrict__ out_q)
{
    __shared__ __align__(16) float s_oW1t[32 * 4];     // [j][d]
    __shared__ __align__(8)  float s_ob1[32];
    __shared__ __align__(16) float s_oW2t[32 * 32];    // [j][i]
    __shared__             float s_ob2[32];
    __shared__ __align__(16) float s_oW3[32 * 16];     // [j][k]
    __shared__ __align__(16) float s_ob3[16];
    __shared__ __align__(16) float s_sW1t[32 * 4];
    __shared__             float s_sb1[32];
    __shared__ __align__(16) float s_sW2t[32 * PSTR];  // [lane][i], padded
    __shared__             float s_sb2[32];
    __shared__             float s_sW3[32 * 16];
    __shared__             float s_sb3[16];
    __shared__ __align__(16) float s_gW1t[32 * PSTR];  // [lane][m], padded
    __shared__             float s_gb1[32];
    __shared__             float s_gW2[64];
    __shared__             float s_gb2[2];

    const int tid = threadIdx.x;

    for (int idx = tid; idx < 128; idx += 256) {
        int d = idx >> 5, j = idx & 31;
        s_oW1t[j * 4 + d] = oW1[idx];
        s_sW1t[j * 4 + d] = sW1[idx];
    }
    for (int idx = tid; idx < 1024; idx += 256) {
        int i = idx >> 5, j = idx & 31;
        s_oW2t[j * 32 + i]   = oW2[idx];
        s_sW2t[j * PSTR + i] = sW2[idx];
        s_gW1t[j * PSTR + i] = gW1[idx];
    }
    for (int idx = tid; idx < 512; idx += 256) {
        s_oW3[idx] = oW3[idx];
        s_sW3[idx] = sW3[idx];
    }
    if (tid < 32) {
        s_ob1[tid] = ob1[tid]; s_ob2[tid] = ob2[tid];
        s_sb1[tid] = sb1[tid]; s_sb2[tid] = sb2[tid];
        s_gb1[tid] = gb1[tid];
    }
    if (tid >= 32 && tid < 48)  s_ob3[tid - 32] = ob3[tid - 32];
    if (tid >= 48 && tid < 64)  s_sb3[tid - 48] = sb3[tid - 48];
    if (tid >= 64 && tid < 128) s_gW2[tid - 64] = gW2[tid - 64];
    if (tid >= 128 && tid < 130) s_gb2[tid - 128] = gb2[tid - 128];
    __syncthreads();

    const int lane = tid & 31;
    const int warp = tid >> 5;
    const int row0 = blockIdx.x * 16 + warp;
    const int row1 = row0 + 8;
    const int sel  = selp[0];

    const float4 xa0 = reinterpret_cast<const float4*>(x)[row0 * 32 + lane];
    const float4 xa1 = reinterpret_cast<const float4*>(x)[row1 * 32 + lane];

    // ---------------- layer 1 (both rows, shared weight fetch) ----------------
    ull h1a[16], h1b[16];   // packed pairs (h1[2t], h1[2t+1])
    #pragma unroll
    for (int t = 0; t < 16; ++t) {
        float4 wA = reinterpret_cast<const float4*>(s_oW1t)[2 * t + 0];
        float4 wB = reinterpret_cast<const float4*>(s_oW1t)[2 * t + 1];
        float2 b2 = reinterpret_cast<const float2*>(s_ob1)[t];
        float e0 = relu_(fmaf(xa0.x, wA.x, fmaf(xa0.y, wA.y, fmaf(xa0.z, wA.z, fmaf(xa0.w, wA.w, b2.x)))));
        float e1 = relu_(fmaf(xa0.x, wB.x, fmaf(xa0.y, wB.y, fmaf(xa0.z, wB.z, fmaf(xa0.w, wB.w, b2.y)))));
        h1a[t] = pk2(e0, e1);
        float f0 = relu_(fmaf(xa1.x, wA.x, fmaf(xa1.y, wA.y, fmaf(xa1.z, wA.z, fmaf(xa1.w, wA.w, b2.x)))));
        float f1 = relu_(fmaf(xa1.x, wB.x, fmaf(xa1.y, wB.y, fmaf(xa1.z, wB.z, fmaf(xa1.w, wB.w, b2.y)))));
        h1b[t] = pk2(f0, f1);
    }

    // acc16 packed: 8 pairs per row, init with ob3
    ull accA[8], accB[8];
    {
        const ull* b3 = reinterpret_cast<const ull*>(s_ob3);
        #pragma unroll
        for (int t = 0; t < 8; ++t) { accA[t] = b3[t]; accB[t] = b3[t]; }
    }

    // ---------------- layer 2 + layer 3 fused (both rows) ----------------
    #pragma unroll 4
    for (int j = 0; j < 32; ++j) {
        ull a0 = 0ull, a1 = 0ull;    // packed (0.f, 0.f)
        const ulonglong2* w2 = reinterpret_cast<const ulonglong2*>(s_oW2t + j * 32);
        #pragma unroll
        for (int q = 0; q < 8; ++q) {
            ulonglong2 w = w2[q];
            a0 = ffma2(h1a[2 * q + 0], w.x, a0);
            a0 = ffma2(h1a[2 * q + 1], w.y, a0);
            a1 = ffma2(h1b[2 * q + 0], w.x, a1);
            a1 = ffma2(h1b[2 * q + 1], w.y, a1);
        }
        float bj = s_ob2[j];
        float l0, h0, l1, h1v;
        upk2(a0, l0, h0);
        upk2(a1, l1, h1v);
        float s0 = relu_(l0 + h0 + bj);
        float s1 = relu_(l1 + h1v + bj);
        ull p0 = pk2(s0, s0);
        ull p1 = pk2(s1, s1);

        const ulonglong2* w3 = reinterpret_cast<const ulonglong2*>(s_oW3 + j * 16);
        #pragma unroll
        for (int r = 0; r < 4; ++r) {
            ulonglong2 w = w3[r];
            accA[2 * r + 0] = ffma2(p0, w.x, accA[2 * r + 0]);
            accA[2 * r + 1] = ffma2(p0, w.y, accA[2 * r + 1]);
            accB[2 * r + 0] = ffma2(p1, w.x, accB[2 * r + 0]);
            accB[2 * r + 1] = ffma2(p1, w.y, accB[2 * r + 1]);
        }
    }

    // final relu + mask (exclude selected agent), then butterfly reduce (packed)
    const float msk = (lane == sel) ? 0.0f : 1.0f;
    #pragma unroll
    for (int t = 0; t < 8; ++t) {
        float lo, hi;
        upk2(accA[t], lo, hi);
        accA[t] = pk2(relu_(lo) * msk, relu_(hi) * msk);
        upk2(accB[t], lo, hi);
        accB[t] = pk2(relu_(lo) * msk, relu_(hi) * msk);
    }
    #pragma unroll
    for (int off = 16; off; off >>= 1) {
        #pragma unroll
        for (int t = 0; t < 8; ++t) {
            accA[t] = fadd2(accA[t], __shfl_xor_sync(FULL, accA[t], off));
            accB[t] = fadd2(accB[t], __shfl_xor_sync(FULL, accB[t], off));
        }
    }

    // ---------------- tail: sel MLP + gating head, per row ----------------
    #pragma unroll
    for (int rr = 0; rr < 2; ++rr) {
        const int row = rr ? row1 : row0;
        const ull* acc = rr ? accB : accA;

        float so[16];
        #pragma unroll
        for (int t = 0; t < 8; ++t) upk2(acc[t], so[2 * t], so[2 * t + 1]);

        // selected agent's input (uniform broadcast load)
        const float4 xs = reinterpret_cast<const float4*>(x)[row * 32 + sel];

        // sel layer1: lane = neuron
        float4 w1 = reinterpret_cast<const float4*>(s_sW1t)[lane];
        float sh1 = relu_(fmaf(xs.x, w1.x, fmaf(xs.y, w1.y, fmaf(xs.z, w1.z, fmaf(xs.w, w1.w, s_sb1[lane])))));

        // sel layer2: lane = neuron, shuffle activations
        float a2 = s_sb2[lane];
        #pragma unroll
        for (int q = 0; q < 8; ++q) {
            float4 w = *reinterpret_cast<const float4*>(s_sW2t + lane * PSTR + 4 * q);
            a2 = fmaf(__shfl_sync(FULL, sh1, 4 * q + 0), w.x, a2);
            a2 = fmaf(__shfl_sync(FULL, sh1, 4 * q + 1), w.y, a2);
            a2 = fmaf(__shfl_sync(FULL, sh1, 4 * q + 2), w.z, a2);
            a2 = fmaf(__shfl_sync(FULL, sh1, 4 * q + 3), w.w, a2);
        }
        const float sh2 = relu_(a2);

        // sel layer3: lanes 0-15 = output dims (16-31 duplicate, harmless)
        const int k15 = lane & 15;
        float a3 = s_sb3[k15];
        #pragma unroll
        for (int j = 0; j < 32; ++j)
            a3 = fmaf(__shfl_sync(FULL, sh2, j), s_sW3[j * 16 + k15], a3);
        const float sel_out = relu_(a3);

        // gating hidden: lane = neuron; concat = [sel_out(16), sum_other(16)]
        float ag = s_gb1[lane];
        #pragma unroll
        for (int m = 0; m < 4; ++m) {
            float4 w = *reinterpret_cast<const float4*>(s_gW1t + lane * PSTR + 4 * m);
            ag = fmaf(__shfl_sync(FULL, sel_out, 4 * m + 0), w.x, ag);
            ag = fmaf(__shfl_sync(FULL, sel_out, 4 * m + 1), w.y, ag);
            ag = fmaf(__shfl_sync(FULL, sel_out, 4 * m + 2), w.z, ag);
            ag = fmaf(__shfl_sync(FULL, sel_out, 4 * m + 3), w.w, ag);
        }
        #pragma unroll
        for (int m = 0; m < 4; ++m) {
            float4 w = *reinterpret_cast<const float4*>(s_gW1t + lane * PSTR + 16 + 4 * m);
            ag = fmaf(so[4 * m + 0], w.x, ag);
            ag = fmaf(so[4 * m + 1], w.y, ag);
            ag = fmaf(so[4 * m + 2], w.z, ag);
            ag = fmaf(so[4 * m + 3], w.w, ag);
        }
        const float hg = relu_(ag);

        float q0 = hg * s_gW2[lane * 2 + 0];
        float q1 = hg * s_gW2[lane * 2 + 1];
        #pragma unroll
        for (int off = 16; off; off >>= 1) {
            q0 += __shfl_xor_sync(FULL, q0, off);
            q1 += __shfl_xor_sync(FULL, q1, off);
        }

        int act = (int)xs.w;               // sel_in[:,3] as int (truncation)
        act = act < 0 ? 0 : (act > 1 ? 1 : act);

        if (lane == 0)
            out_q[row] = (act == 0) ? (q0 + s_gb2[0]) : (q1 + s_gb2[1]);
    }
}

extern "C" void kernel_launch(void* const* d_in, const int* in_sizes, int n_in,
                              void* d_out, int out_size)
{
    (void)in_sizes; (void)n_in; (void)out_size;
    // B = 65536 rows; 8 warps/block x 2 rows/warp = 16 rows/block -> 4096 blocks.
    dqv_kernel<<<4096, 256>>>(
        (const float*)d_in[0],  (const int*)d_in[1],
        (const float*)d_in[2],  (const float*)d_in[3],
        (const float*)d_in[4],  (const float*)d_in[5],
        (const float*)d_in[6],  (const float*)d_in[7],
        (const float*)d_in[8],  (const float*)d_in[9],
        (const float*)d_in[10], (const float*)d_in[11],
        (const float*)d_in[12], (const float*)d_in[13],
        (const float*)d_in[14], (const float*)d_in[15],
        (const float*)d_in[16], (const float*)d_in[17],
        (float*)d_out);
}

// round 4
// speedup vs baseline: 2.8426x; 1.3475x over previous
#include <cuda_runtime.h>

#define FULL 0xffffffffu
typedef unsigned long long ull;

__device__ __forceinline__ float relu_(float v) { return fmaxf(v, 0.0f); }

__device__ __forceinline__ ull ffma2(ull a, ull b, ull c) {
    ull d; asm("fma.rn.f32x2 %0, %1, %2, %3;" : "=l"(d) : "l"(a), "l"(b), "l"(c)); return d;
}
__device__ __forceinline__ ull fadd2(ull a, ull b) {
    ull d; asm("add.rn.f32x2 %0, %1, %2;" : "=l"(d) : "l"(a), "l"(b)); return d;
}
__device__ __forceinline__ ull pk2(float lo, float hi) {
    ull r; asm("mov.b64 %0, {%1, %2};" : "=l"(r) : "f"(lo), "f"(hi)); return r;
}
__device__ __forceinline__ void upk2(ull v, float& lo, float& hi) {
    asm("mov.b64 {%0, %1}, %2;" : "=f"(lo), "=f"(hi) : "l"(v));
}

// ---------------- constant blob layout (floats) ----------------
// [0]    oW1t [j*4+d]   (128)
// [128]  ob1           (32)
// [160]  oW2t [j*32+i] (1024)
// [1184] ob2           (32)
// [1216] oW3  [j*16+k] (512)
// [1728] ob3           (16)
#define CW_TOTAL 1744
__constant__ __align__(16) float c_w[CW_TOTAL];
__device__   __align__(16) float g_blob[CW_TOTAL];

__global__ void pack_kernel(const float* __restrict__ oW1, const float* __restrict__ ob1,
                            const float* __restrict__ oW2, const float* __restrict__ ob2,
                            const float* __restrict__ oW3, const float* __restrict__ ob3)
{
    int t = threadIdx.x;
    // oW1t[j*4+d] = oW1[d*32+j]
    if (t < 128) { int j = t >> 2, d = t & 3; g_blob[t] = oW1[d * 32 + j]; }
    if (t < 32) g_blob[128 + t] = ob1[t];
    // oW2t[j*32+i] = oW2[i*32+j]
    for (int idx = t; idx < 1024; idx += 256) {
        int j = idx >> 5, i = idx & 31;
        g_blob[160 + j * 32 + i] = oW2[i * 32 + j];
    }
    if (t < 32) g_blob[1184 + t] = ob2[t];
    for (int idx = t; idx < 512; idx += 256) g_blob[1216 + idx] = oW3[idx];
    if (t < 16) g_blob[1728 + t] = ob3[t];
}

// Padded stride for lane-indexed shared tables (bank-conflict-free)
#define PSTR 36

// One warp handles TWO batch rows; lane = agent. Main-loop weights come from
// the constant/uniform port (LDCU), freeing L1tex. Tail tables stay in shared.
__global__ __launch_bounds__(256, 2)
void dqv_kernel(const float* __restrict__ x,
                const int*   __restrict__ selp,
                const float* __restrict__ sW1, const float* __restrict__ sb1,
                const float* __restrict__ sW2, const float* __restrict__ sb2,
                const float* __restrict__ sW3, const float* __restrict__ sb3,
                const float* __restrict__ gW1, const float* __restrict__ gb1,
                const float* __restrict__ gW2, const float* __restrict__ gb2,
                float* __restrict__ out_q)
{
    __shared__ __align__(16) float s_sW1t[32 * 4];
    __shared__             float s_sb1[32];
    __shared__ __align__(16) float s_sW2t[32 * PSTR];
    __shared__             float s_sb2[32];
    __shared__             float s_sW3[32 * 16];
    __shared__             float s_sb3[16];
    __shared__ __align__(16) float s_gW1t[32 * PSTR];
    __shared__             float s_gb1[32];
    __shared__             float s_gW2[64];
    __shared__             float s_gb2[2];

    const int tid = threadIdx.x;

    for (int idx = tid; idx < 128; idx += 256) {
        int d = idx >> 5, j = idx & 31;
        s_sW1t[j * 4 + d] = sW1[idx];
    }
    for (int idx = tid; idx < 1024; idx += 256) {
        int i = idx >> 5, j = idx & 31;
        s_sW2t[j * PSTR + i] = sW2[idx];
        s_gW1t[j * PSTR + i] = gW1[idx];
    }
    for (int idx = tid; idx < 512; idx += 256) s_sW3[idx] = sW3[idx];
    if (tid < 32) { s_sb1[tid] = sb1[tid]; s_sb2[tid] = sb2[tid]; s_gb1[tid] = gb1[tid]; }
    if (tid >= 48 && tid < 64)  s_sb3[tid - 48] = sb3[tid - 48];
    if (tid >= 64 && tid < 128) s_gW2[tid - 64] = gW2[tid - 64];
    if (tid >= 128 && tid < 130) s_gb2[tid - 128] = gb2[tid - 128];
    __syncthreads();

    const int lane = tid & 31;
    const int warp = tid >> 5;
    const int row0 = blockIdx.x * 16 + warp;
    const int row1 = row0 + 8;
    const int sel  = selp[0];

    const float4 xa0 = reinterpret_cast<const float4*>(x)[row0 * 32 + lane];
    const float4 xa1 = reinterpret_cast<const float4*>(x)[row1 * 32 + lane];

    // ---------------- layer 1 (constant weights) ----------------
    ull h1a[16], h1b[16];
    #pragma unroll
    for (int t = 0; t < 16; ++t) {
        float4 wA = reinterpret_cast<const float4*>(c_w)[2 * t + 0];
        float4 wB = reinterpret_cast<const float4*>(c_w)[2 * t + 1];
        float b0 = c_w[128 + 2 * t], b1v = c_w[128 + 2 * t + 1];
        float e0 = relu_(fmaf(xa0.x, wA.x, fmaf(xa0.y, wA.y, fmaf(xa0.z, wA.z, fmaf(xa0.w, wA.w, b0)))));
        float e1 = relu_(fmaf(xa0.x, wB.x, fmaf(xa0.y, wB.y, fmaf(xa0.z, wB.z, fmaf(xa0.w, wB.w, b1v)))));
        h1a[t] = pk2(e0, e1);
        float f0 = relu_(fmaf(xa1.x, wA.x, fmaf(xa1.y, wA.y, fmaf(xa1.z, wA.z, fmaf(xa1.w, wA.w, b0)))));
        float f1 = relu_(fmaf(xa1.x, wB.x, fmaf(xa1.y, wB.y, fmaf(xa1.z, wB.z, fmaf(xa1.w, wB.w, b1v)))));
        h1b[t] = pk2(f0, f1);
    }

    ull accA[8], accB[8];
    {
        const ull* b3 = reinterpret_cast<const ull*>(c_w + 1728);
        #pragma unroll
        for (int t = 0; t < 8; ++t) { accA[t] = b3[t]; accB[t] = b3[t]; }
    }

    // ---------------- layer 2 + layer 3 fused (constant weights) ----------------
    #pragma unroll 4
    for (int j = 0; j < 32; ++j) {
        ull a0 = 0ull, a1 = 0ull;
        const ulonglong2* w2 = reinterpret_cast<const ulonglong2*>(c_w + 160 + j * 32);
        #pragma unroll
        for (int q = 0; q < 8; ++q) {
            ulonglong2 w = w2[q];
            a0 = ffma2(h1a[2 * q + 0], w.x, a0);
            a0 = ffma2(h1a[2 * q + 1], w.y, a0);
            a1 = ffma2(h1b[2 * q + 0], w.x, a1);
            a1 = ffma2(h1b[2 * q + 1], w.y, a1);
        }
        float bj = c_w[1184 + j];
        float l0, h0, l1, h1v;
        upk2(a0, l0, h0);
        upk2(a1, l1, h1v);
        float s0 = relu_(l0 + h0 + bj);
        float s1 = relu_(l1 + h1v + bj);
        ull p0 = pk2(s0, s0);
        ull p1 = pk2(s1, s1);

        const ulonglong2* w3 = reinterpret_cast<const ulonglong2*>(c_w + 1216 + j * 16);
        #pragma unroll
        for (int r = 0; r < 4; ++r) {
            ulonglong2 w = w3[r];
            accA[2 * r + 0] = ffma2(p0, w.x, accA[2 * r + 0]);
            accA[2 * r + 1] = ffma2(p0, w.y, accA[2 * r + 1]);
            accB[2 * r + 0] = ffma2(p1, w.x, accB[2 * r + 0]);
            accB[2 * r + 1] = ffma2(p1, w.y, accB[2 * r + 1]);
        }
    }

    // final relu + mask + packed butterfly reduce
    const float msk = (lane == sel) ? 0.0f : 1.0f;
    #pragma unroll
    for (int t = 0; t < 8; ++t) {
        float lo, hi;
        upk2(accA[t], lo, hi);
        accA[t] = pk2(relu_(lo) * msk, relu_(hi) * msk);
        upk2(accB[t], lo, hi);
        accB[t] = pk2(relu_(lo) * msk, relu_(hi) * msk);
    }
    #pragma unroll
    for (int off = 16; off; off >>= 1) {
        #pragma unroll
        for (int t = 0; t < 8; ++t) {
            accA[t] = fadd2(accA[t], __shfl_xor_sync(FULL, accA[t], off));
            accB[t] = fadd2(accB[t], __shfl_xor_sync(FULL, accB[t], off));
        }
    }

    // ---------------- tail: sel MLP + gating head ----------------
    #pragma unroll
    for (int rr = 0; rr < 2; ++rr) {
        const int row = rr ? row1 : row0;
        const ull* acc = rr ? accB : accA;

        float so[16];
        #pragma unroll
        for (int t = 0; t < 8; ++t) upk2(acc[t], so[2 * t], so[2 * t + 1]);

        const float4 xs = reinterpret_cast<const float4*>(x)[row * 32 + sel];

        float4 w1 = reinterpret_cast<const float4*>(s_sW1t)[lane];
        float sh1 = relu_(fmaf(xs.x, w1.x, fmaf(xs.y, w1.y, fmaf(xs.z, w1.z, fmaf(xs.w, w1.w, s_sb1[lane])))));

        float a2 = s_sb2[lane];
        #pragma unroll
        for (int q = 0; q < 8; ++q) {
            float4 w = *reinterpret_cast<const float4*>(s_sW2t + lane * PSTR + 4 * q);
            a2 = fmaf(__shfl_sync(FULL, sh1, 4 * q + 0), w.x, a2);
            a2 = fmaf(__shfl_sync(FULL, sh1, 4 * q + 1), w.y, a2);
            a2 = fmaf(__shfl_sync(FULL, sh1, 4 * q + 2), w.z, a2);
            a2 = fmaf(__shfl_sync(FULL, sh1, 4 * q + 3), w.w, a2);
        }
        const float sh2 = relu_(a2);

        const int k15 = lane & 15;
        float a3 = s_sb3[k15];
        #pragma unroll
        for (int j = 0; j < 32; ++j)
            a3 = fmaf(__shfl_sync(FULL, sh2, j), s_sW3[j * 16 + k15], a3);
        const float sel_out = relu_(a3);

        float ag = s_gb1[lane];
        #pragma unroll
        for (int m = 0; m < 4; ++m) {
            float4 w = *reinterpret_cast<const float4*>(s_gW1t + lane * PSTR + 4 * m);
            ag = fmaf(__shfl_sync(FULL, sel_out, 4 * m + 0), w.x, ag);
            ag = fmaf(__shfl_sync(FULL, sel_out, 4 * m + 1), w.y, ag);
            ag = fmaf(__shfl_sync(FULL, sel_out, 4 * m + 2), w.z, ag);
            ag = fmaf(__shfl_sync(FULL, sel_out, 4 * m + 3), w.w, ag);
        }
        #pragma unroll
        for (int m = 0; m < 4; ++m) {
            float4 w = *reinterpret_cast<const float4*>(s_gW1t + lane * PSTR + 16 + 4 * m);
            ag = fmaf(so[4 * m + 0], w.x, ag);
            ag = fmaf(so[4 * m + 1], w.y, ag);
            ag = fmaf(so[4 * m + 2], w.z, ag);
            ag = fmaf(so[4 * m + 3], w.w, ag);
        }
        const float hg = relu_(ag);

        float q0 = hg * s_gW2[lane * 2 + 0];
        float q1 = hg * s_gW2[lane * 2 + 1];
        #pragma unroll
        for (int off = 16; off; off >>= 1) {
            q0 += __shfl_xor_sync(FULL, q0, off);
            q1 += __shfl_xor_sync(FULL, q1, off);
        }

        int act = (int)xs.w;
        act = act < 0 ? 0 : (act > 1 ? 1 : act);

        if (lane == 0)
            out_q[row] = (act == 0) ? (q0 + s_gb2[0]) : (q1 + s_gb2[1]);
    }
}

extern "C" void kernel_launch(void* const* d_in, const int* in_sizes, int n_in,
                              void* d_out, int out_size)
{
    (void)in_sizes; (void)n_in; (void)out_size;

    // 1) gather/transpose other-agent MLP weights into a device blob
    pack_kernel<<<1, 256>>>(
        (const float*)d_in[2], (const float*)d_in[3],
        (const float*)d_in[4], (const float*)d_in[5],
        (const float*)d_in[6], (const float*)d_in[7]);

    // 2) blob -> constant bank. Resolve BOTH symbols to real device addresses
    //    (passing g_blob's host shadow as a device src was round-3's bug).
    void* dst = nullptr;
    void* src = nullptr;
    cudaGetSymbolAddress(&dst, c_w);
    cudaGetSymbolAddress(&src, g_blob);
    cudaMemcpyAsync(dst, src, CW_TOTAL * sizeof(float),
                    cudaMemcpyDeviceToDevice, 0);

    // 3) main kernel: B = 65536 rows; 8 warps x 2 rows = 16 rows/block
    dqv_kernel<<<4096, 256>>>(
        (const float*)d_in[0],  (const int*)d_in[1],
        (const float*)d_in[8],  (const float*)d_in[9],
        (const float*)d_in[10], (const float*)d_in[11],
        (const float*)d_in[12], (const float*)d_in[13],
        (const float*)d_in[14], (const float*)d_in[15],
        (const float*)d_in[16], (const float*)d_in[17],
        (float*)d_out);
}